// round 14
// baseline (speedup 1.0000x reference)
#include <cuda_runtime.h>
#include <cuda_fp16.h>
#include <math.h>
#include <stdint.h>

// B=2, N=2048, C=1024, H=16, D=64
#define NB 2
#define NN 2048
#define NC 1024
#define NH 16
#define ND 64
#define NTOK (NB * NN)

// ---------------- scratch ----------------
__device__ __half g_xt[NTOK * NC];          // x fp16
__device__ __half g_wqkv[3 * NC * NC];      // qkv_w fp16
__device__ __half g_wproj[NC * NC];         // proj_w fp16
__device__ __half g_qkv[NTOK * 3 * NC];     // GEMM1 out fp16
__device__ __half g_q[NTOK * NC];           // [bh][n][d] fp16, scaled 0.125/T[h]
__device__ __half g_k[NTOK * NC];           // [bh][n][d] fp16, scaled 0.125
__device__ __half g_v[NTOK * NC];           // [bh][d][n] fp16 TRANSPOSED
__device__ __half g_att[NTOK * NC];         // attention out fp16, token-major

// ---------------- PTX helpers ----------------
__device__ __forceinline__ uint32_t smem_u32(const void* p) {
    return (uint32_t)__cvta_generic_to_shared(p);
}
__device__ __forceinline__ void ldm_x4(uint32_t& r0, uint32_t& r1,
                                       uint32_t& r2, uint32_t& r3, uint32_t addr) {
    asm volatile("ldmatrix.sync.aligned.m8n8.x4.shared.b16 {%0,%1,%2,%3}, [%4];"
                 : "=r"(r0), "=r"(r1), "=r"(r2), "=r"(r3) : "r"(addr));
}
__device__ __forceinline__ void mma_f16(float* c, const uint32_t* a,
                                        uint32_t b0, uint32_t b1) {
    asm volatile(
        "mma.sync.aligned.m16n8k16.row.col.f32.f16.f16.f32 "
        "{%0,%1,%2,%3}, {%4,%5,%6,%7}, {%8,%9}, {%0,%1,%2,%3};"
        : "+f"(c[0]), "+f"(c[1]), "+f"(c[2]), "+f"(c[3])
        : "r"(a[0]), "r"(a[1]), "r"(a[2]), "r"(a[3]), "r"(b0), "r"(b1));
}
// fp16-accumulated mma: D,C are 2 packed half2 regs (row r / row r+8)
__device__ __forceinline__ void mma_f16h(uint32_t* c, const uint32_t* a,
                                         uint32_t b0, uint32_t b1) {
    asm volatile(
        "mma.sync.aligned.m16n8k16.row.col.f16.f16.f16.f16 "
        "{%0,%1}, {%2,%3,%4,%5}, {%6,%7}, {%0,%1};"
        : "+r"(c[0]), "+r"(c[1])
        : "r"(a[0]), "r"(a[1]), "r"(a[2]), "r"(a[3]), "r"(b0), "r"(b1));
}
__device__ __forceinline__ void cp_async16(uint32_t saddr, const void* gptr) {
    asm volatile("cp.async.cg.shared.global [%0], [%1], 16;"
                 :: "r"(saddr), "l"(gptr));
}
#define CP_COMMIT() asm volatile("cp.async.commit_group;" ::: "memory")
#define CP_WAIT(n)  asm volatile("cp.async.wait_group %0;" :: "n"(n) : "memory")

__device__ __forceinline__ uint32_t h2_bits(float a, float b) {
    __half2 h = __floats2half2_rn(a, b);
    return *(uint32_t*)&h;
}
__device__ __forceinline__ uint32_t h2b(__half2 h) { return *(uint32_t*)&h; }

// =============================================================================
// fused fp32 -> fp16 conversion of x, qkv_w, proj_w (one launch)
// =============================================================================
#define N8_X   (NTOK * NC / 8)
#define N8_WQ  (3 * NC * NC / 8)
#define N8_WP  (NC * NC / 8)

__global__ __launch_bounds__(256) void cvt3_f16_kernel(
    const float4* __restrict__ sx, uint4* __restrict__ dx,
    const float4* __restrict__ swq, uint4* __restrict__ dwq,
    const float4* __restrict__ swp, uint4* __restrict__ dwp)
{
    int i = blockIdx.x * 256 + threadIdx.x;
    const float4* s;
    uint4* d;
    if (i < N8_X)                { s = sx + 2 * i;  d = dx + i; }
    else if (i < N8_X + N8_WQ)   { int j = i - N8_X;  s = swq + 2 * j; d = dwq + j; }
    else                         { int j = i - N8_X - N8_WQ; s = swp + 2 * j; d = dwp + j; }
    float4 a = s[0], b = s[1];
    uint4 o;
    o.x = h2_bits(a.x, a.y); o.y = h2_bits(a.z, a.w);
    o.z = h2_bits(b.x, b.y); o.w = h2_bits(b.z, b.w);
    *d = o;
}

// =============================================================================
// FP16 GEMM (ROUND-7 RING, measured fastest): C = A*B^T (+bias), fp32 accum,
// fp32 or fp16 out. CTA 128x128, 128 threads (2x2 warps of 64x64), Ktile=32.
// 4-stage cp.async ring, ONE sync/iter, issue(kt+3) AFTER compute,
// wait_group(2) -> 3 tiles of prefetch. 80 KB smem -> 2 CTAs/SM.
// =============================================================================
#define GKH   32
#define GROWH 40
#define G_STAGE_BYTES (128 * GROWH * 2 * 2)    // 20480
#define G_SMEM_TOTAL  (4 * G_STAGE_BYTES)      // 81920

template <bool HAS_BIAS, bool OUT_HALF>
__global__ __launch_bounds__(128) void gemm_f16(
    const __half* __restrict__ A, const __half* __restrict__ Bm,
    const float* __restrict__ bias, void* __restrict__ Cv,
    int M, int Nc, int K)
{
    extern __shared__ __align__(128) char gsm[];
    const uint32_t sbase0 = smem_u32(gsm);

    const int t = threadIdx.x;
    const int w = t >> 5, lane = t & 31;
    const int wm = w >> 1, wn = w & 1;

    const __half* Ab = A  + (size_t)(blockIdx.y * 128) * K;
    const __half* Bb = Bm + (size_t)(blockIdx.x * 128) * K;

    const int a_row  = (lane & 7) + ((lane >> 3) & 1) * 8;
    const int a_colh = (lane >> 4) << 3;
    const int b_row  = (lane & 7) + ((lane >> 4) << 3);
    const int b_colh = ((lane >> 3) & 1) * 8;

    float acc[4][8][4];
#pragma unroll
    for (int mi = 0; mi < 4; mi++)
#pragma unroll
        for (int ni = 0; ni < 8; ni++)
#pragma unroll
            for (int j = 0; j < 4; j++) acc[mi][ni][j] = 0.0f;

    const int NT = K >> 5;

    auto issue = [&](int kt) {
        const uint32_t sb = sbase0 + (kt & 3) * G_STAGE_BYTES;
#pragma unroll
        for (int i = 0; i < 8; i++) {
            int c = t + i * 128;
            int mat = c >> 9;
            int r   = (c >> 2) & 127;
            int q   = c & 3;
            const __half* g = (mat ? Bb : Ab) + (size_t)r * K + kt * GKH + q * 8;
            uint32_t sa = sb + (uint32_t)(mat * (128 * GROWH) + r * GROWH + q * 8) * 2;
            cp_async16(sa, g);
        }
        CP_COMMIT();
    };

    issue(0); issue(1); issue(2);

    for (int kt = 0; kt < NT; kt++) {
        const uint32_t as = sbase0 + (kt & 3) * G_STAGE_BYTES;
        const uint32_t bs = as + 128 * GROWH * 2;

        CP_WAIT(2);
        __syncthreads();

#pragma unroll
        for (int ks = 0; ks < 2; ks++) {
            const int kc = ks * 16;
            uint32_t a[4][4];
#pragma unroll
            for (int mi = 0; mi < 4; mi++)
                ldm_x4(a[mi][0], a[mi][1], a[mi][2], a[mi][3],
                       as + ((wm * 64 + mi * 16 + a_row) * GROWH + kc + a_colh) * 2);
            uint32_t b[4][4];
#pragma unroll
            for (int np = 0; np < 4; np++)
                ldm_x4(b[np][0], b[np][1], b[np][2], b[np][3],
                       bs + ((wn * 64 + np * 16 + b_row) * GROWH + kc + b_colh) * 2);
#pragma unroll
            for (int mi = 0; mi < 4; mi++)
#pragma unroll
                for (int ni = 0; ni < 8; ni++)
                    mma_f16(acc[mi][ni], a[mi],
                            b[ni >> 1][(ni & 1) * 2], b[ni >> 1][(ni & 1) * 2 + 1]);
        }

        if (kt + 3 < NT) issue(kt + 3);
        else             CP_COMMIT();      // keep wait_group(2) arithmetic exact
    }

    const int erow0 = blockIdx.y * 128 + wm * 64 + (lane >> 2);
    const int ecol0 = blockIdx.x * 128 + wn * 64 + (lane & 3) * 2;
#pragma unroll
    for (int mi = 0; mi < 4; mi++) {
#pragma unroll
        for (int ni = 0; ni < 8; ni++) {
            int r = erow0 + mi * 16;
            int c = ecol0 + ni * 8;
            float2 v01 = make_float2(acc[mi][ni][0], acc[mi][ni][1]);
            float2 v23 = make_float2(acc[mi][ni][2], acc[mi][ni][3]);
            if (HAS_BIAS) {
                float b0 = bias[c], b1 = bias[c + 1];
                v01.x += b0; v01.y += b1;
                v23.x += b0; v23.y += b1;
            }
            if (OUT_HALF) {
                __half* Ch = (__half*)Cv;
                *(uint32_t*)(Ch + (size_t)r * Nc + c)       = h2_bits(v01.x, v01.y);
                *(uint32_t*)(Ch + (size_t)(r + 8) * Nc + c) = h2_bits(v23.x, v23.y);
            } else {
                float* Cf = (float*)Cv;
                *(float2*)(Cf + (size_t)r * Nc + c)       = v01;
                *(float2*)(Cf + (size_t)(r + 8) * Nc + c) = v23;
            }
        }
    }
}

// =============================================================================
// Normalize q,k over full C (fp16 in, fp32 sums); q scaled 0.125/T[h],
// k scaled 0.125; fp16 out. v -> transposed [bh][d][n] fp16.
// =============================================================================
__global__ __launch_bounds__(256) void norm_split_kernel(
    const __half* __restrict__ qkv, const float* __restrict__ temp,
    __half* __restrict__ q, __half* __restrict__ k, __half* __restrict__ v)
{
    const int tok = blockIdx.x;
    const int b = tok >> 11;
    const int n = tok & 2047;
    const __half* row = qkv + (size_t)tok * (3 * NC);
    const int t = threadIdx.x;

    __half2 q01 = *(const __half2*)(row + t * 4);
    __half2 q23 = *(const __half2*)(row + t * 4 + 2);
    __half2 k01 = *(const __half2*)(row + NC + t * 4);
    __half2 k23 = *(const __half2*)(row + NC + t * 4 + 2);
    __half2 v01 = *(const __half2*)(row + 2 * NC + t * 4);
    __half2 v23 = *(const __half2*)(row + 2 * NC + t * 4 + 2);

    float2 qa = __half22float2(q01), qb = __half22float2(q23);
    float2 ka = __half22float2(k01), kb = __half22float2(k23);

    float sq = qa.x * qa.x + qa.y * qa.y + qb.x * qb.x + qb.y * qb.y;
    float sk = ka.x * ka.x + ka.y * ka.y + kb.x * kb.x + kb.y * kb.y;
#pragma unroll
    for (int m = 16; m > 0; m >>= 1) {
        sq += __shfl_xor_sync(0xffffffffu, sq, m);
        sk += __shfl_xor_sync(0xffffffffu, sk, m);
    }
    __shared__ float red[2][8];
    const int warp = t >> 5, lane = t & 31;
    if (lane == 0) { red[0][warp] = sq; red[1][warp] = sk; }
    __syncthreads();
    float sqt = 0.f, skt = 0.f;
#pragma unroll
    for (int w = 0; w < 8; w++) { sqt += red[0][w]; skt += red[1][w]; }

    const int h = t >> 4;
    const float qs = 0.125f / fmaxf(sqrtf(sqt), 1e-12f) / temp[h];
    const float ks = 0.125f / fmaxf(sqrtf(skt), 1e-12f);

    const int d = (t & 15) * 4;
    const size_t qoff = ((size_t)(b * NH + h) * NN + n) * ND + d;
    uint2 qo = make_uint2(h2_bits(qa.x * qs, qa.y * qs), h2_bits(qb.x * qs, qb.y * qs));
    uint2 ko = make_uint2(h2_bits(ka.x * ks, ka.y * ks), h2_bits(kb.x * ks, kb.y * ks));
    *(uint2*)&q[qoff] = qo;
    *(uint2*)&k[qoff] = ko;

    const size_t vbase = ((size_t)(b * NH + h) * ND + d) * NN + n;
    v[vbase]          = __low2half(v01);
    v[vbase + NN]     = __high2half(v01);
    v[vbase + 2 * NN] = __low2half(v23);
    v[vbase + 3 * NN] = __high2half(v23);
}

// =============================================================================
// Attention fp16 v5: 3-stage K/V ring, ONE sync/iter (issue(it+2) right after
// the sync; write stage (it+2)%3 == (it-1)%3 was drained by that sync), two
// tiles in flight during compute. S in fp16 C-frags; Taylor exp (2xHFMA2);
// O fp32. 128-thread CTAs (4 warps x 16 q-rows), 64.5 KB smem -> 3 CTAs/SM.
// SMEM (halves, stride 72): Qs[64] | Kst[3][64] | Vst[3][64]
// =============================================================================
#define AH 72
#define QS_OFF  0
#define KST_OFF (64 * AH)
#define VST_OFF (KST_OFF + 3 * 64 * AH)
#define STAGE_B (64 * AH * 2)                            // 9216 B per stage
#define ATTN_SMEM_BYTES ((VST_OFF + 3 * 64 * AH) * 2)    // 64512

__global__ __launch_bounds__(128, 3) void attn_kernel(
    const __half* __restrict__ q, const __half* __restrict__ k,
    const __half* __restrict__ v, __half* __restrict__ att)
{
    extern __shared__ __align__(128) __half smemh[];
    const uint32_t sb = smem_u32(smemh);

    const int t = threadIdx.x;
    const int w = t >> 5, lane = t & 31;
    const int qtile = blockIdx.x;                 // 0..31 (64 rows each)
    const int bh = blockIdx.y;
    const int b = bh >> 4, h = bh & 15;

    const __half* qg = q + ((size_t)bh * NN + qtile * 64) * ND;
    const __half* kg = k + (size_t)bh * NN * ND;
    const __half* vg = v + (size_t)bh * ND * NN;  // [d][n]

    const int a_row  = (lane & 7) + ((lane >> 3) & 1) * 8;
    const int a_colh = (lane >> 4) << 3;
    const int b_row  = (lane & 7) + ((lane >> 4) << 3);
    const int b_colh = ((lane >> 3) & 1) * 8;

    // ---- Q preload ----
#pragma unroll
    for (int i = 0; i < 4; i++) {
        int c = t + i * 128;
        int r = c >> 3, ch = c & 7;
        *(uint4*)(smemh + QS_OFF + r * AH + ch * 8) =
            *(const uint4*)(qg + (size_t)r * ND + ch * 8);
    }

    // ---- producer precompute: 8 chunks/thread (4 K + 4 V) ----
    uint32_t soff[8];
    const __half* gp[8];
#pragma unroll
    for (int i = 0; i < 8; i++) {
        int c = t + i * 128;
        int mat = c >> 9;
        int r   = (c >> 3) & 63;
        int ch  = c & 7;
        soff[i] = sb + (uint32_t)((mat ? VST_OFF : KST_OFF) + r * AH + ch * 8) * 2;
        gp[i]   = mat ? (vg + (size_t)r * NN + ch * 8)
                      : (kg + (size_t)r * ND + ch * 8);
    }
    auto issue = [&](int it) {
        const uint32_t stageb = (uint32_t)(it % 3) * STAGE_B;
        const int advK = it * (64 * ND);
        const int advV = it * 64;
#pragma unroll
        for (int i = 0; i < 4; i++) cp_async16(soff[i] + stageb, gp[i] + advK);
#pragma unroll
        for (int i = 4; i < 8; i++) cp_async16(soff[i] + stageb, gp[i] + advV);
        CP_COMMIT();
    };

    issue(0); issue(1);

    // ---- hoist Q A-fragments (loop-invariant) ----
    __syncthreads();
    uint32_t aq[4][4];
#pragma unroll
    for (int ks = 0; ks < 4; ks++)
        ldm_x4(aq[ks][0], aq[ks][1], aq[ks][2], aq[ks][3],
               sb + (uint32_t)((w * 16 + a_row) * AH + ks * 16 + a_colh) * 2);

    float o[8][4];
#pragma unroll
    for (int ni = 0; ni < 8; ni++)
#pragma unroll
        for (int j = 0; j < 4; j++) o[ni][j] = 0.0f;
    float lsum0 = 0.0f, lsum1 = 0.0f;

    const __half2 ONE  = __floats2half2_rn(1.0f, 1.0f);
    const __half2 HALF = __floats2half2_rn(0.5f, 0.5f);

    const int NITER = NN / 64;

    for (int it = 0; it < NITER; it++) {
        const uint32_t stageb = (uint32_t)(it % 3) * STAGE_B;
        const uint32_t ks_base = sb + KST_OFF * 2 + stageb;
        const uint32_t vs_base = sb + VST_OFF * 2 + stageb;

        CP_WAIT(1);            // stage it landed (it+1 may be in flight)
        __syncthreads();       // all warps done with stage it-1 (last iter)

        if (it + 2 < NITER) issue(it + 2);   // writes (it+2)%3 == (it-1)%3
        else                CP_COMMIT();     // keep wait_group(1) exact

        // ---- S = Q K^T, fp16 accumulate ----
        uint32_t s[8][2];
#pragma unroll
        for (int ni = 0; ni < 8; ni++) { s[ni][0] = 0u; s[ni][1] = 0u; }

#pragma unroll
        for (int ks = 0; ks < 4; ks++) {
            const int kc = ks * 16;
            uint32_t bb[4][4];
#pragma unroll
            for (int np = 0; np < 4; np++)
                ldm_x4(bb[np][0], bb[np][1], bb[np][2], bb[np][3],
                       ks_base + ((np * 16 + b_row) * AH + kc + b_colh) * 2);
#pragma unroll
            for (int ni = 0; ni < 8; ni++)
                mma_f16h(s[ni], aq[ks], bb[ni >> 1][(ni & 1) * 2],
                         bb[ni >> 1][(ni & 1) * 2 + 1]);
        }

        // ---- Taylor exp (2x HFMA2) -> PV A-fragments directly ----
        __half2 acc0 = __floats2half2_rn(0.f, 0.f), acc1 = acc0;
#pragma unroll
        for (int kk = 0; kk < 4; kk++) {
            __half2 x0 = *(__half2*)&s[2 * kk][0];
            __half2 x1 = *(__half2*)&s[2 * kk][1];
            __half2 x2 = *(__half2*)&s[2 * kk + 1][0];
            __half2 x3 = *(__half2*)&s[2 * kk + 1][1];
            __half2 e0 = __hfma2(x0, __hfma2(x0, HALF, ONE), ONE);
            __half2 e1 = __hfma2(x1, __hfma2(x1, HALF, ONE), ONE);
            __half2 e2 = __hfma2(x2, __hfma2(x2, HALF, ONE), ONE);
            __half2 e3 = __hfma2(x3, __hfma2(x3, HALF, ONE), ONE);
            acc0 = __hadd2(acc0, __hadd2(e0, e2));
            acc1 = __hadd2(acc1, __hadd2(e1, e3));

            uint32_t pa[4];
            pa[0] = h2b(e0); pa[1] = h2b(e1); pa[2] = h2b(e2); pa[3] = h2b(e3);

            const int kc = kk * 16;
            uint32_t bb[4][4];
#pragma unroll
            for (int np = 0; np < 4; np++)
                ldm_x4(bb[np][0], bb[np][1], bb[np][2], bb[np][3],
                       vs_base + ((np * 16 + b_row) * AH + kc + b_colh) * 2);
#pragma unroll
            for (int ni = 0; ni < 8; ni++)
                mma_f16(o[ni], pa, bb[ni >> 1][(ni & 1) * 2],
                        bb[ni >> 1][(ni & 1) * 2 + 1]);
        }
        {
            float2 f;
            f = __half22float2(acc0); lsum0 += f.x + f.y;
            f = __half22float2(acc1); lsum1 += f.x + f.y;
        }
    }

    lsum0 += __shfl_xor_sync(0xffffffffu, lsum0, 1);
    lsum0 += __shfl_xor_sync(0xffffffffu, lsum0, 2);
    lsum1 += __shfl_xor_sync(0xffffffffu, lsum1, 1);
    lsum1 += __shfl_xor_sync(0xffffffffu, lsum1, 2);
    const float inv0 = 1.0f / lsum0;
    const float inv1 = 1.0f / lsum1;

    const int prow0 = w * 16 + (lane >> 2);
    const int pcol0 = (lane & 3) * 2;
    const int grow0 = qtile * 64 + prow0;
#pragma unroll
    for (int ni = 0; ni < 8; ni++) {
        const int col = h * ND + ni * 8 + pcol0;
        *(uint32_t*)(att + (size_t)(b * NN + grow0) * NC + col) =
            h2_bits(o[ni][0] * inv0, o[ni][1] * inv0);
        *(uint32_t*)(att + (size_t)(b * NN + grow0 + 8) * NC + col) =
            h2_bits(o[ni][2] * inv1, o[ni][3] * inv1);
    }
}

// =============================================================================
// Launch
// =============================================================================
extern "C" void kernel_launch(void* const* d_in, const int* in_sizes, int n_in,
                              void* d_out, int out_size)
{
    (void)in_sizes; (void)n_in; (void)out_size;
    const float* x      = (const float*)d_in[0];
    const float* qkv_w  = (const float*)d_in[1];
    const float* temp   = (const float*)d_in[2];
    const float* proj_w = (const float*)d_in[3];
    const float* proj_b = (const float*)d_in[4];
    float* out = (float*)d_out;

    __half *p_xt, *p_wqkv, *p_wproj, *p_qkv, *p_q, *p_k, *p_v, *p_att;
    cudaGetSymbolAddress((void**)&p_xt,    g_xt);
    cudaGetSymbolAddress((void**)&p_wqkv,  g_wqkv);
    cudaGetSymbolAddress((void**)&p_wproj, g_wproj);
    cudaGetSymbolAddress((void**)&p_qkv,   g_qkv);
    cudaGetSymbolAddress((void**)&p_q,     g_q);
    cudaGetSymbolAddress((void**)&p_k,     g_k);
    cudaGetSymbolAddress((void**)&p_v,     g_v);
    cudaGetSymbolAddress((void**)&p_att,   g_att);

    cudaFuncSetAttribute((const void*)gemm_f16<false, true>,
                         cudaFuncAttributeMaxDynamicSharedMemorySize, G_SMEM_TOTAL);
    cudaFuncSetAttribute((const void*)gemm_f16<true, false>,
                         cudaFuncAttributeMaxDynamicSharedMemorySize, G_SMEM_TOTAL);
    cudaFuncSetAttribute(attn_kernel,
                         cudaFuncAttributeMaxDynamicSharedMemorySize, ATTN_SMEM_BYTES);
    cudaFuncSetAttribute(attn_kernel,
                         cudaFuncAttributePreferredSharedMemoryCarveout, 100);

    cvt3_f16_kernel<<<(N8_X + N8_WQ + N8_WP) / 256, 256>>>(
        (const float4*)x, (uint4*)p_xt,
        (const float4*)qkv_w, (uint4*)p_wqkv,
        (const float4*)proj_w, (uint4*)p_wproj);

    // 1) QKV GEMM (fp16 out)
    gemm_f16<false, true><<<dim3(3 * NC / 128, NTOK / 128), 128, G_SMEM_TOTAL>>>(
        p_xt, p_wqkv, nullptr, p_qkv, NTOK, 3 * NC, NC);

    // 2) normalize + head split
    norm_split_kernel<<<NTOK, 256>>>(p_qkv, temp, p_q, p_k, p_v);

    // 3) attention (3-stage ring, one sync/iter)
    attn_kernel<<<dim3(NN / 64, NB * NH), 128, ATTN_SMEM_BYTES>>>(
        p_q, p_k, p_v, p_att);

    // 4) projection (fp32 out + bias)
    gemm_f16<true, false><<<dim3(NC / 128, NTOK / 128), 128, G_SMEM_TOTAL>>>(
        p_att, p_wproj, proj_b, out, NTOK, NC, NC);
}

// round 15
// speedup vs baseline: 1.0157x; 1.0157x over previous
#include <cuda_runtime.h>
#include <cuda_fp16.h>
#include <math.h>
#include <stdint.h>

// B=2, N=2048, C=1024, H=16, D=64
#define NB 2
#define NN 2048
#define NC 1024
#define NH 16
#define ND 64
#define NTOK (NB * NN)

// ---------------- scratch ----------------
__device__ __half g_xt[NTOK * NC];          // x fp16
__device__ __half g_wqkv[3 * NC * NC];      // qkv_w fp16
__device__ __half g_wproj[NC * NC];         // proj_w fp16
__device__ __half g_qkv[NTOK * 3 * NC];     // GEMM1 out fp16
__device__ __half g_q[NTOK * NC];           // [bh][n][d] fp16, scaled 0.125/T[h]
__device__ __half g_k[NTOK * NC];           // [bh][n][d] fp16, scaled 0.125
__device__ __half g_v[NTOK * NC];           // [bh][d][n] fp16 TRANSPOSED
__device__ __half g_att[NTOK * NC];         // attention out fp16, token-major

// ---------------- PTX helpers ----------------
__device__ __forceinline__ uint32_t smem_u32(const void* p) {
    return (uint32_t)__cvta_generic_to_shared(p);
}
__device__ __forceinline__ void ldm_x4(uint32_t& r0, uint32_t& r1,
                                       uint32_t& r2, uint32_t& r3, uint32_t addr) {
    asm volatile("ldmatrix.sync.aligned.m8n8.x4.shared.b16 {%0,%1,%2,%3}, [%4];"
                 : "=r"(r0), "=r"(r1), "=r"(r2), "=r"(r3) : "r"(addr));
}
__device__ __forceinline__ void mma_f16(float* c, const uint32_t* a,
                                        uint32_t b0, uint32_t b1) {
    asm volatile(
        "mma.sync.aligned.m16n8k16.row.col.f32.f16.f16.f32 "
        "{%0,%1,%2,%3}, {%4,%5,%6,%7}, {%8,%9}, {%0,%1,%2,%3};"
        : "+f"(c[0]), "+f"(c[1]), "+f"(c[2]), "+f"(c[3])
        : "r"(a[0]), "r"(a[1]), "r"(a[2]), "r"(a[3]), "r"(b0), "r"(b1));
}
// fp16-accumulated mma: D,C are 2 packed half2 regs (row r / row r+8)
__device__ __forceinline__ void mma_f16h(uint32_t* c, const uint32_t* a,
                                         uint32_t b0, uint32_t b1) {
    asm volatile(
        "mma.sync.aligned.m16n8k16.row.col.f16.f16.f16.f16 "
        "{%0,%1}, {%2,%3,%4,%5}, {%6,%7}, {%0,%1};"
        : "+r"(c[0]), "+r"(c[1])
        : "r"(a[0]), "r"(a[1]), "r"(a[2]), "r"(a[3]), "r"(b0), "r"(b1));
}
__device__ __forceinline__ void cp_async16(uint32_t saddr, const void* gptr) {
    asm volatile("cp.async.cg.shared.global [%0], [%1], 16;"
                 :: "r"(saddr), "l"(gptr));
}
#define CP_COMMIT() asm volatile("cp.async.commit_group;" ::: "memory")
#define CP_WAIT(n)  asm volatile("cp.async.wait_group %0;" :: "n"(n) : "memory")

__device__ __forceinline__ uint32_t h2_bits(float a, float b) {
    __half2 h = __floats2half2_rn(a, b);
    return *(uint32_t*)&h;
}
__device__ __forceinline__ uint32_t h2b(__half2 h) { return *(uint32_t*)&h; }

// =============================================================================
// fused fp32 -> fp16 conversion of x, qkv_w, proj_w (one launch)
// =============================================================================
#define N8_X   (NTOK * NC / 8)
#define N8_WQ  (3 * NC * NC / 8)
#define N8_WP  (NC * NC / 8)

__global__ __launch_bounds__(256) void cvt3_f16_kernel(
    const float4* __restrict__ sx, uint4* __restrict__ dx,
    const float4* __restrict__ swq, uint4* __restrict__ dwq,
    const float4* __restrict__ swp, uint4* __restrict__ dwp)
{
    int i = blockIdx.x * 256 + threadIdx.x;
    const float4* s;
    uint4* d;
    if (i < N8_X)                { s = sx + 2 * i;  d = dx + i; }
    else if (i < N8_X + N8_WQ)   { int j = i - N8_X;  s = swq + 2 * j; d = dwq + j; }
    else                         { int j = i - N8_X - N8_WQ; s = swp + 2 * j; d = dwp + j; }
    float4 a = s[0], b = s[1];
    uint4 o;
    o.x = h2_bits(a.x, a.y); o.y = h2_bits(a.z, a.w);
    o.z = h2_bits(b.x, b.y); o.w = h2_bits(b.z, b.w);
    *d = o;
}

// =============================================================================
// FP16 GEMM (ROUND-7 RING, measured fastest): C = A*B^T (+bias), fp32 accum,
// fp32 or fp16 out. CTA 128x128, 128 threads (2x2 warps of 64x64), Ktile=32.
// 4-stage cp.async ring, ONE sync/iter, issue(kt+3) AFTER compute,
// wait_group(2) -> 3 tiles of prefetch. 80 KB smem -> 2 CTAs/SM.
// =============================================================================
#define GKH   32
#define GROWH 40
#define G_STAGE_BYTES (128 * GROWH * 2 * 2)    // 20480
#define G_SMEM_TOTAL  (4 * G_STAGE_BYTES)      // 81920

template <bool HAS_BIAS, bool OUT_HALF>
__global__ __launch_bounds__(128) void gemm_f16(
    const __half* __restrict__ A, const __half* __restrict__ Bm,
    const float* __restrict__ bias, void* __restrict__ Cv,
    int M, int Nc, int K)
{
    extern __shared__ __align__(128) char gsm[];
    const uint32_t sbase0 = smem_u32(gsm);

    const int t = threadIdx.x;
    const int w = t >> 5, lane = t & 31;
    const int wm = w >> 1, wn = w & 1;

    const __half* Ab = A  + (size_t)(blockIdx.y * 128) * K;
    const __half* Bb = Bm + (size_t)(blockIdx.x * 128) * K;

    const int a_row  = (lane & 7) + ((lane >> 3) & 1) * 8;
    const int a_colh = (lane >> 4) << 3;
    const int b_row  = (lane & 7) + ((lane >> 4) << 3);
    const int b_colh = ((lane >> 3) & 1) * 8;

    float acc[4][8][4];
#pragma unroll
    for (int mi = 0; mi < 4; mi++)
#pragma unroll
        for (int ni = 0; ni < 8; ni++)
#pragma unroll
            for (int j = 0; j < 4; j++) acc[mi][ni][j] = 0.0f;

    const int NT = K >> 5;

    auto issue = [&](int kt) {
        const uint32_t sb = sbase0 + (kt & 3) * G_STAGE_BYTES;
#pragma unroll
        for (int i = 0; i < 8; i++) {
            int c = t + i * 128;
            int mat = c >> 9;
            int r   = (c >> 2) & 127;
            int q   = c & 3;
            const __half* g = (mat ? Bb : Ab) + (size_t)r * K + kt * GKH + q * 8;
            uint32_t sa = sb + (uint32_t)(mat * (128 * GROWH) + r * GROWH + q * 8) * 2;
            cp_async16(sa, g);
        }
        CP_COMMIT();
    };

    issue(0); issue(1); issue(2);

    for (int kt = 0; kt < NT; kt++) {
        const uint32_t as = sbase0 + (kt & 3) * G_STAGE_BYTES;
        const uint32_t bs = as + 128 * GROWH * 2;

        CP_WAIT(2);
        __syncthreads();

#pragma unroll
        for (int ks = 0; ks < 2; ks++) {
            const int kc = ks * 16;
            uint32_t a[4][4];
#pragma unroll
            for (int mi = 0; mi < 4; mi++)
                ldm_x4(a[mi][0], a[mi][1], a[mi][2], a[mi][3],
                       as + ((wm * 64 + mi * 16 + a_row) * GROWH + kc + a_colh) * 2);
            uint32_t b[4][4];
#pragma unroll
            for (int np = 0; np < 4; np++)
                ldm_x4(b[np][0], b[np][1], b[np][2], b[np][3],
                       bs + ((wn * 64 + np * 16 + b_row) * GROWH + kc + b_colh) * 2);
#pragma unroll
            for (int mi = 0; mi < 4; mi++)
#pragma unroll
                for (int ni = 0; ni < 8; ni++)
                    mma_f16(acc[mi][ni], a[mi],
                            b[ni >> 1][(ni & 1) * 2], b[ni >> 1][(ni & 1) * 2 + 1]);
        }

        if (kt + 3 < NT) issue(kt + 3);
        else             CP_COMMIT();      // keep wait_group(2) arithmetic exact
    }

    const int erow0 = blockIdx.y * 128 + wm * 64 + (lane >> 2);
    const int ecol0 = blockIdx.x * 128 + wn * 64 + (lane & 3) * 2;
#pragma unroll
    for (int mi = 0; mi < 4; mi++) {
#pragma unroll
        for (int ni = 0; ni < 8; ni++) {
            int r = erow0 + mi * 16;
            int c = ecol0 + ni * 8;
            float2 v01 = make_float2(acc[mi][ni][0], acc[mi][ni][1]);
            float2 v23 = make_float2(acc[mi][ni][2], acc[mi][ni][3]);
            if (HAS_BIAS) {
                float b0 = bias[c], b1 = bias[c + 1];
                v01.x += b0; v01.y += b1;
                v23.x += b0; v23.y += b1;
            }
            if (OUT_HALF) {
                __half* Ch = (__half*)Cv;
                *(uint32_t*)(Ch + (size_t)r * Nc + c)       = h2_bits(v01.x, v01.y);
                *(uint32_t*)(Ch + (size_t)(r + 8) * Nc + c) = h2_bits(v23.x, v23.y);
            } else {
                float* Cf = (float*)Cv;
                *(float2*)(Cf + (size_t)r * Nc + c)       = v01;
                *(float2*)(Cf + (size_t)(r + 8) * Nc + c) = v23;
            }
        }
    }
}

// =============================================================================
// Normalize q,k over full C (fp16 in, fp32 sums); q scaled 0.125/T[h],
// k scaled 0.125; fp16 out. v -> transposed [bh][d][n] fp16.
// =============================================================================
__global__ __launch_bounds__(256) void norm_split_kernel(
    const __half* __restrict__ qkv, const float* __restrict__ temp,
    __half* __restrict__ q, __half* __restrict__ k, __half* __restrict__ v)
{
    const int tok = blockIdx.x;
    const int b = tok >> 11;
    const int n = tok & 2047;
    const __half* row = qkv + (size_t)tok * (3 * NC);
    const int t = threadIdx.x;

    __half2 q01 = *(const __half2*)(row + t * 4);
    __half2 q23 = *(const __half2*)(row + t * 4 + 2);
    __half2 k01 = *(const __half2*)(row + NC + t * 4);
    __half2 k23 = *(const __half2*)(row + NC + t * 4 + 2);
    __half2 v01 = *(const __half2*)(row + 2 * NC + t * 4);
    __half2 v23 = *(const __half2*)(row + 2 * NC + t * 4 + 2);

    float2 qa = __half22float2(q01), qb = __half22float2(q23);
    float2 ka = __half22float2(k01), kb = __half22float2(k23);

    float sq = qa.x * qa.x + qa.y * qa.y + qb.x * qb.x + qb.y * qb.y;
    float sk = ka.x * ka.x + ka.y * ka.y + kb.x * kb.x + kb.y * kb.y;
#pragma unroll
    for (int m = 16; m > 0; m >>= 1) {
        sq += __shfl_xor_sync(0xffffffffu, sq, m);
        sk += __shfl_xor_sync(0xffffffffu, sk, m);
    }
    __shared__ float red[2][8];
    const int warp = t >> 5, lane = t & 31;
    if (lane == 0) { red[0][warp] = sq; red[1][warp] = sk; }
    __syncthreads();
    float sqt = 0.f, skt = 0.f;
#pragma unroll
    for (int w = 0; w < 8; w++) { sqt += red[0][w]; skt += red[1][w]; }

    const int h = t >> 4;
    const float qs = 0.125f / fmaxf(sqrtf(sqt), 1e-12f) / temp[h];
    const float ks = 0.125f / fmaxf(sqrtf(skt), 1e-12f);

    const int d = (t & 15) * 4;
    const size_t qoff = ((size_t)(b * NH + h) * NN + n) * ND + d;
    uint2 qo = make_uint2(h2_bits(qa.x * qs, qa.y * qs), h2_bits(qb.x * qs, qb.y * qs));
    uint2 ko = make_uint2(h2_bits(ka.x * ks, ka.y * ks), h2_bits(kb.x * ks, kb.y * ks));
    *(uint2*)&q[qoff] = qo;
    *(uint2*)&k[qoff] = ko;

    const size_t vbase = ((size_t)(b * NH + h) * ND + d) * NN + n;
    v[vbase]          = __low2half(v01);
    v[vbase + NN]     = __high2half(v01);
    v[vbase + 2 * NN] = __low2half(v23);
    v[vbase + 3 * NN] = __high2half(v23);
}

// =============================================================================
// Attention fp16 v6: 32 q-rows per warp (two m16 fragments) -> each K/V
// ldmatrix feeds 2x the HMMA (1 LDSM : 4 HMMA). CTA = 4 warps x 32 rows =
// 128 q-rows; 2-stage K/V ring (R13 style, 2 syncs/iter); S in fp16 C-frags;
// Taylor exp (2xHFMA2); O fp32. SMEM: Qs[128] | Kst[2][64] | Vst[2][64],
// stride 72 halves = 55296 B; ~190 regs -> 2 CTAs/SM.
// =============================================================================
#define AH 72
#define QS_OFF  0
#define KST_OFF (128 * AH)
#define VST_OFF (KST_OFF + 2 * 64 * AH)
#define STAGE_B (64 * AH * 2)
#define ATTN_SMEM_BYTES ((VST_OFF + 2 * 64 * AH) * 2)   // 55296

__global__ __launch_bounds__(128, 2) void attn_kernel(
    const __half* __restrict__ q, const __half* __restrict__ k,
    const __half* __restrict__ v, __half* __restrict__ att)
{
    extern __shared__ __align__(128) __half smemh[];
    const uint32_t sb = smem_u32(smemh);

    const int t = threadIdx.x;
    const int w = t >> 5, lane = t & 31;
    const int qtile = blockIdx.x;                 // 0..15 (128 rows each)
    const int bh = blockIdx.y;
    const int b = bh >> 4, h = bh & 15;

    const __half* qg = q + ((size_t)bh * NN + qtile * 128) * ND;
    const __half* kg = k + (size_t)bh * NN * ND;
    const __half* vg = v + (size_t)bh * ND * NN;  // [d][n]

    const int a_row  = (lane & 7) + ((lane >> 3) & 1) * 8;
    const int a_colh = (lane >> 4) << 3;
    const int b_row  = (lane & 7) + ((lane >> 4) << 3);
    const int b_colh = ((lane >> 3) & 1) * 8;

    // ---- Q preload: 128 rows x 8 chunks = 1024 chunks, 8/thread ----
#pragma unroll
    for (int i = 0; i < 8; i++) {
        int c = t + i * 128;
        int r = c >> 3, ch = c & 7;
        *(uint4*)(smemh + QS_OFF + r * AH + ch * 8) =
            *(const uint4*)(qg + (size_t)r * ND + ch * 8);
    }

    // ---- producer precompute: 8 chunks/thread (4 K + 4 V) ----
    uint32_t soff[8];
    const __half* gp[8];
#pragma unroll
    for (int i = 0; i < 8; i++) {
        int c = t + i * 128;
        int mat = c >> 9;
        int r   = (c >> 3) & 63;
        int ch  = c & 7;
        soff[i] = sb + (uint32_t)((mat ? VST_OFF : KST_OFF) + r * AH + ch * 8) * 2;
        gp[i]   = mat ? (vg + (size_t)r * NN + ch * 8)
                      : (kg + (size_t)r * ND + ch * 8);
    }
    auto issue = [&](int it) {
        const uint32_t stageb = (it & 1) ? STAGE_B : 0;
        const int advK = it * (64 * ND);
        const int advV = it * 64;
#pragma unroll
        for (int i = 0; i < 4; i++) cp_async16(soff[i] + stageb, gp[i] + advK);
#pragma unroll
        for (int i = 4; i < 8; i++) cp_async16(soff[i] + stageb, gp[i] + advV);
        CP_COMMIT();
    };

    issue(0); issue(1);

    // ---- hoist Q A-fragments for BOTH 16-row tiles (loop-invariant) ----
    __syncthreads();
    uint32_t aq[2][4][4];
#pragma unroll
    for (int mi = 0; mi < 2; mi++)
#pragma unroll
        for (int ks = 0; ks < 4; ks++)
            ldm_x4(aq[mi][ks][0], aq[mi][ks][1], aq[mi][ks][2], aq[mi][ks][3],
                   sb + (uint32_t)((w * 32 + mi * 16 + a_row) * AH + ks * 16 + a_colh) * 2);

    float o[2][8][4];
#pragma unroll
    for (int mi = 0; mi < 2; mi++)
#pragma unroll
        for (int ni = 0; ni < 8; ni++)
#pragma unroll
            for (int j = 0; j < 4; j++) o[mi][ni][j] = 0.0f;
    float lsum[2][2] = {{0.f, 0.f}, {0.f, 0.f}};

    const __half2 ONE  = __floats2half2_rn(1.0f, 1.0f);
    const __half2 HALF = __floats2half2_rn(0.5f, 0.5f);

    const int NITER = NN / 64;

    for (int it = 0; it < NITER; it++) {
        const uint32_t stageb = (it & 1) ? STAGE_B : 0;
        const uint32_t ks_base = sb + KST_OFF * 2 + stageb;
        const uint32_t vs_base = sb + VST_OFF * 2 + stageb;

        CP_WAIT(1);
        __syncthreads();

        // ---- S = Q K^T, fp16 accumulate, both 16-row tiles share K frags ----
        uint32_t s[2][8][2];
#pragma unroll
        for (int mi = 0; mi < 2; mi++)
#pragma unroll
            for (int ni = 0; ni < 8; ni++) { s[mi][ni][0] = 0u; s[mi][ni][1] = 0u; }

#pragma unroll
        for (int ks = 0; ks < 4; ks++) {
            const int kc = ks * 16;
            uint32_t bb[4][4];
#pragma unroll
            for (int np = 0; np < 4; np++)
                ldm_x4(bb[np][0], bb[np][1], bb[np][2], bb[np][3],
                       ks_base + ((np * 16 + b_row) * AH + kc + b_colh) * 2);
#pragma unroll
            for (int mi = 0; mi < 2; mi++)
#pragma unroll
                for (int ni = 0; ni < 8; ni++)
                    mma_f16h(s[mi][ni], aq[mi][ks], bb[ni >> 1][(ni & 1) * 2],
                             bb[ni >> 1][(ni & 1) * 2 + 1]);
        }

        // ---- Taylor exp -> PV A-frags; V frags shared across both tiles ----
#pragma unroll
        for (int kk = 0; kk < 4; kk++) {
            uint32_t pa[2][4];
#pragma unroll
            for (int mi = 0; mi < 2; mi++) {
                __half2 x0 = *(__half2*)&s[mi][2 * kk][0];
                __half2 x1 = *(__half2*)&s[mi][2 * kk][1];
                __half2 x2 = *(__half2*)&s[mi][2 * kk + 1][0];
                __half2 x3 = *(__half2*)&s[mi][2 * kk + 1][1];
                __half2 e0 = __hfma2(x0, __hfma2(x0, HALF, ONE), ONE);
                __half2 e1 = __hfma2(x1, __hfma2(x1, HALF, ONE), ONE);
                __half2 e2 = __hfma2(x2, __hfma2(x2, HALF, ONE), ONE);
                __half2 e3 = __hfma2(x3, __hfma2(x3, HALF, ONE), ONE);
                __half2 sa = __hadd2(e0, e2);
                __half2 sbv = __hadd2(e1, e3);
                float2 fa = __half22float2(sa);
                float2 fb = __half22float2(sbv);
                lsum[mi][0] += fa.x + fa.y;
                lsum[mi][1] += fb.x + fb.y;
                pa[mi][0] = h2b(e0); pa[mi][1] = h2b(e1);
                pa[mi][2] = h2b(e2); pa[mi][3] = h2b(e3);
            }

            const int kc = kk * 16;
            uint32_t bb[4][4];
#pragma unroll
            for (int np = 0; np < 4; np++)
                ldm_x4(bb[np][0], bb[np][1], bb[np][2], bb[np][3],
                       vs_base + ((np * 16 + b_row) * AH + kc + b_colh) * 2);
#pragma unroll
            for (int mi = 0; mi < 2; mi++)
#pragma unroll
                for (int ni = 0; ni < 8; ni++)
                    mma_f16(o[mi][ni], pa[mi], bb[ni >> 1][(ni & 1) * 2],
                            bb[ni >> 1][(ni & 1) * 2 + 1]);
        }

        __syncthreads();
        if (it + 2 < NITER) issue(it + 2);
        else                CP_COMMIT();
    }

    // ---- reduce row sums across quads; write out both tiles ----
    const int prow0 = w * 32 + (lane >> 2);
    const int pcol0 = (lane & 3) * 2;
#pragma unroll
    for (int mi = 0; mi < 2; mi++) {
        float l0 = lsum[mi][0], l1 = lsum[mi][1];
        l0 += __shfl_xor_sync(0xffffffffu, l0, 1);
        l0 += __shfl_xor_sync(0xffffffffu, l0, 2);
        l1 += __shfl_xor_sync(0xffffffffu, l1, 1);
        l1 += __shfl_xor_sync(0xffffffffu, l1, 2);
        const float inv0 = 1.0f / l0;
        const float inv1 = 1.0f / l1;
        const int grow0 = qtile * 128 + prow0 + mi * 16;
#pragma unroll
        for (int ni = 0; ni < 8; ni++) {
            const int col = h * ND + ni * 8 + pcol0;
            *(uint32_t*)(att + (size_t)(b * NN + grow0) * NC + col) =
                h2_bits(o[mi][ni][0] * inv0, o[mi][ni][1] * inv0);
            *(uint32_t*)(att + (size_t)(b * NN + grow0 + 8) * NC + col) =
                h2_bits(o[mi][ni][2] * inv1, o[mi][ni][3] * inv1);
        }
    }
}

// =============================================================================
// Launch
// =============================================================================
extern "C" void kernel_launch(void* const* d_in, const int* in_sizes, int n_in,
                              void* d_out, int out_size)
{
    (void)in_sizes; (void)n_in; (void)out_size;
    const float* x      = (const float*)d_in[0];
    const float* qkv_w  = (const float*)d_in[1];
    const float* temp   = (const float*)d_in[2];
    const float* proj_w = (const float*)d_in[3];
    const float* proj_b = (const float*)d_in[4];
    float* out = (float*)d_out;

    __half *p_xt, *p_wqkv, *p_wproj, *p_qkv, *p_q, *p_k, *p_v, *p_att;
    cudaGetSymbolAddress((void**)&p_xt,    g_xt);
    cudaGetSymbolAddress((void**)&p_wqkv,  g_wqkv);
    cudaGetSymbolAddress((void**)&p_wproj, g_wproj);
    cudaGetSymbolAddress((void**)&p_qkv,   g_qkv);
    cudaGetSymbolAddress((void**)&p_q,     g_q);
    cudaGetSymbolAddress((void**)&p_k,     g_k);
    cudaGetSymbolAddress((void**)&p_v,     g_v);
    cudaGetSymbolAddress((void**)&p_att,   g_att);

    cudaFuncSetAttribute((const void*)gemm_f16<false, true>,
                         cudaFuncAttributeMaxDynamicSharedMemorySize, G_SMEM_TOTAL);
    cudaFuncSetAttribute((const void*)gemm_f16<true, false>,
                         cudaFuncAttributeMaxDynamicSharedMemorySize, G_SMEM_TOTAL);
    cudaFuncSetAttribute(attn_kernel,
                         cudaFuncAttributeMaxDynamicSharedMemorySize, ATTN_SMEM_BYTES);
    cudaFuncSetAttribute(attn_kernel,
                         cudaFuncAttributePreferredSharedMemoryCarveout, 100);

    cvt3_f16_kernel<<<(N8_X + N8_WQ + N8_WP) / 256, 256>>>(
        (const float4*)x, (uint4*)p_xt,
        (const float4*)qkv_w, (uint4*)p_wqkv,
        (const float4*)proj_w, (uint4*)p_wproj);

    // 1) QKV GEMM (fp16 out)
    gemm_f16<false, true><<<dim3(3 * NC / 128, NTOK / 128), 128, G_SMEM_TOTAL>>>(
        p_xt, p_wqkv, nullptr, p_qkv, NTOK, 3 * NC, NC);

    // 2) normalize + head split
    norm_split_kernel<<<NTOK, 256>>>(p_qkv, temp, p_q, p_k, p_v);

    // 3) attention (32 q-rows/warp, 2-stage ring)
    attn_kernel<<<dim3(NN / 128, NB * NH), 128, ATTN_SMEM_BYTES>>>(
        p_q, p_k, p_v, p_att);

    // 4) projection (fp32 out + bias)
    gemm_f16<true, false><<<dim3(NC / 128, NTOK / 128), 128, G_SMEM_TOTAL>>>(
        p_att, p_wproj, proj_b, out, NTOK, NC, NC);
}